// round 1
// baseline (speedup 1.0000x reference)
#include <cuda_runtime.h>
#include <cuda_bf16.h>

// Problem constants
#define BB 2
#define SS 2048
#define DD 1024
#define HH 16
#define DEPTH 64

#define OUT_ELEMS   (BB * SS * DD)                    // 4,194,304
#define ATTN_ELEMS  ((long long)BB * HH * SS * SS)    // 134,217,728

// Scratch (device globals; no allocation in kernel_launch)
__device__ float g_Qp[BB * SS * DD];
__device__ float g_Kp[BB * SS * DD];
__device__ float g_Vp[BB * SS * DD];
__device__ float g_Ctx[BB * SS * DD];
__device__ float g_AttnScratch[BB * HH * SS * SS];    // fallback if attn not in d_out

// ---------------------------------------------------------------------------
// Tiled SGEMM: C = alpha * A @ op(B) (+ bias)
//   A: [M,K] row-major, leading dim lda
//   B: !TRANSB -> [K,N] ldb ; TRANSB -> [N,K] ldb (computes A @ B^T)
//   C: [M,N] ldc
// Batched over blockIdx.z = b*Hn + h with per-b / per-h strides.
// Tiles: BM=BN=64, BK=16, 256 threads, 4x4 register microtile.
// Requires M%64==0, N%64==0, K%16==0 (true for all our shapes).
// ---------------------------------------------------------------------------
template <bool TRANSB>
__global__ void __launch_bounds__(256)
gemm64(const float* __restrict__ A, const float* __restrict__ B,
       const float* __restrict__ bias, float* __restrict__ C,
       int M, int N, int K, int lda, int ldb, int ldc,
       long long sAb, long long sAh, long long sBb, long long sBh,
       long long sCb, long long sCh, int Hn, float alpha)
{
    __shared__ float As[16][64];
    __shared__ float Bs[16][64];

    const int z = blockIdx.z;
    const int b = z / Hn, h = z % Hn;
    A += (long long)b * sAb + (long long)h * sAh;
    B += (long long)b * sBb + (long long)h * sBh;
    C += (long long)b * sCb + (long long)h * sCh;

    const int m0 = blockIdx.y * 64;
    const int n0 = blockIdx.x * 64;
    const int tid = threadIdx.x;
    const int tx = tid & 15;       // 0..15 -> 4 cols each
    const int ty = tid >> 4;       // 0..15 -> 4 rows each

    float acc[4][4] = {};

    for (int k0 = 0; k0 < K; k0 += 16) {
        // Load A tile (64 rows x 16 k) transposed into As[k][m]
        #pragma unroll
        for (int i = 0; i < 4; i++) {
            int idx = tid + i * 256;          // 0..1023
            int m = idx >> 4, kk = idx & 15;
            As[kk][m] = A[(long long)(m0 + m) * lda + (k0 + kk)];
        }
        // Load B tile into Bs[k][n]
        if (TRANSB) {
            #pragma unroll
            for (int i = 0; i < 4; i++) {
                int idx = tid + i * 256;
                int n = idx >> 4, kk = idx & 15;
                Bs[kk][n] = B[(long long)(n0 + n) * ldb + (k0 + kk)];
            }
        } else {
            #pragma unroll
            for (int i = 0; i < 4; i++) {
                int idx = tid + i * 256;
                int kk = idx >> 6, n = idx & 63;
                Bs[kk][n] = B[(long long)(k0 + kk) * ldb + (n0 + n)];
            }
        }
        __syncthreads();

        #pragma unroll
        for (int kk = 0; kk < 16; kk++) {
            float4 a4 = *(const float4*)&As[kk][ty * 4];
            float4 b4 = *(const float4*)&Bs[kk][tx * 4];
            float av[4] = {a4.x, a4.y, a4.z, a4.w};
            float bv[4] = {b4.x, b4.y, b4.z, b4.w};
            #pragma unroll
            for (int i = 0; i < 4; i++)
                #pragma unroll
                for (int j = 0; j < 4; j++)
                    acc[i][j] += av[i] * bv[j];
        }
        __syncthreads();
    }

    #pragma unroll
    for (int i = 0; i < 4; i++) {
        int m = m0 + ty * 4 + i;
        #pragma unroll
        for (int j = 0; j < 4; j++) {
            int n = n0 + tx * 4 + j;
            float val = alpha * acc[i][j];
            if (bias) val += bias[n];
            C[(long long)m * ldc + n] = val;
        }
    }
}

// ---------------------------------------------------------------------------
// Fused mask + softmax over one attn row (length S=2048) per block.
// attn holds raw scaled logits on entry; holds probabilities on exit.
// mask shape (B, 1, S, S); 1.0 = masked.
// ---------------------------------------------------------------------------
__global__ void __launch_bounds__(256)
softmax_mask(float* __restrict__ attn, const float* __restrict__ mask)
{
    const long long row = blockIdx.x;          // 0 .. B*H*S-1
    const int qi = (int)(row % SS);
    const int b  = (int)(row / ((long long)HH * SS));
    float* p = attn + row * SS;
    const float* mrow = mask + ((long long)b * SS + qi) * SS;

    const int tid = threadIdx.x;               // 256 threads, 8 elems each
    float v[8];
    float mx = -1e30f;
    #pragma unroll
    for (int i = 0; i < 8; i++) {
        int c = tid + i * 256;
        v[i] = p[c] + mrow[c] * (-1e9f);
        mx = fmaxf(mx, v[i]);
    }

    __shared__ float red[32];
    // block max
    #pragma unroll
    for (int o = 16; o > 0; o >>= 1)
        mx = fmaxf(mx, __shfl_xor_sync(0xffffffffu, mx, o));
    if ((tid & 31) == 0) red[tid >> 5] = mx;
    __syncthreads();
    if (tid < 32) {
        float t = (tid < 8) ? red[tid] : -1e30f;
        #pragma unroll
        for (int o = 4; o > 0; o >>= 1)
            t = fmaxf(t, __shfl_xor_sync(0xffffffffu, t, o));
        if (tid == 0) red[0] = t;
    }
    __syncthreads();
    mx = red[0];
    __syncthreads();

    float sum = 0.f;
    #pragma unroll
    for (int i = 0; i < 8; i++) {
        v[i] = __expf(v[i] - mx);
        sum += v[i];
    }
    // block sum
    #pragma unroll
    for (int o = 16; o > 0; o >>= 1)
        sum += __shfl_xor_sync(0xffffffffu, sum, o);
    if ((tid & 31) == 0) red[tid >> 5] = sum;
    __syncthreads();
    if (tid < 32) {
        float t = (tid < 8) ? red[tid] : 0.f;
        #pragma unroll
        for (int o = 4; o > 0; o >>= 1)
            t += __shfl_xor_sync(0xffffffffu, t, o);
        if (tid == 0) red[0] = t;
    }
    __syncthreads();
    const float inv = 1.f / red[0];

    #pragma unroll
    for (int i = 0; i < 8; i++)
        p[tid + i * 256] = v[i] * inv;
}

// ---------------------------------------------------------------------------
extern "C" void kernel_launch(void* const* d_in, const int* in_sizes, int n_in,
                              void* d_out, int out_size)
{
    const float* v    = (const float*)d_in[0];
    const float* k    = (const float*)d_in[1];
    const float* q    = (const float*)d_in[2];
    const float* mask = (const float*)d_in[3];
    const float* wq   = (const float*)d_in[4];
    const float* bq   = (const float*)d_in[5];
    const float* wk   = (const float*)d_in[6];
    const float* bk   = (const float*)d_in[7];
    const float* wv   = (const float*)d_in[8];
    const float* bv   = (const float*)d_in[9];
    const float* wo   = (const float*)d_in[10];
    const float* bo   = (const float*)d_in[11];

    float *Qp, *Kp, *Vp, *Ctx, *AttnScratch;
    cudaGetSymbolAddress((void**)&Qp,  g_Qp);
    cudaGetSymbolAddress((void**)&Kp,  g_Kp);
    cudaGetSymbolAddress((void**)&Vp,  g_Vp);
    cudaGetSymbolAddress((void**)&Ctx, g_Ctx);
    cudaGetSymbolAddress((void**)&AttnScratch, g_AttnScratch);

    float* out = (float*)d_out;
    // If the harness output is the full tuple (out, attn), attn lives in d_out.
    float* attn = ((long long)out_size >= (long long)OUT_ELEMS + ATTN_ELEMS)
                      ? out + OUT_ELEMS
                      : AttnScratch;

    const int M = BB * SS;              // 4096
    const float scale = 0.125f;         // 1/sqrt(64)

    // 1) Projections: [4096,1024] @ [1024,1024] + bias
    {
        dim3 grid(DD / 64, M / 64, 1), blk(256);
        gemm64<false><<<grid, blk>>>(q, wq, bq, Qp, M, DD, DD, DD, DD, DD,
                                     0, 0, 0, 0, 0, 0, 1, 1.f);
        gemm64<false><<<grid, blk>>>(k, wk, bk, Kp, M, DD, DD, DD, DD, DD,
                                     0, 0, 0, 0, 0, 0, 1, 1.f);
        gemm64<false><<<grid, blk>>>(v, wv, bv, Vp, M, DD, DD, DD, DD, DD,
                                     0, 0, 0, 0, 0, 0, 1, 1.f);
    }

    // 2) Logits: per (b,h): [2048,64] @ [2048,64]^T * scale -> attn
    {
        dim3 grid(SS / 64, SS / 64, BB * HH), blk(256);
        gemm64<true><<<grid, blk>>>(Qp, Kp, nullptr, attn,
                                    SS, SS, DEPTH, DD, DD, SS,
                                    (long long)SS * DD, DEPTH,
                                    (long long)SS * DD, DEPTH,
                                    (long long)HH * SS * SS, (long long)SS * SS,
                                    HH, scale);
    }

    // 3) Mask + softmax, in place over attn rows
    {
        dim3 grid(BB * HH * SS), blk(256);
        softmax_mask<<<grid, blk>>>(attn, mask);
    }

    // 4) Context: per (b,h): [2048,2048] @ [2048,64] -> Ctx in (b,s,h,d) layout
    {
        dim3 grid(DEPTH / 64, SS / 64, BB * HH), blk(256);
        gemm64<false><<<grid, blk>>>(attn, Vp, nullptr, Ctx,
                                     SS, DEPTH, SS, SS, DD, DD,
                                     (long long)HH * SS * SS, (long long)SS * SS,
                                     (long long)SS * DD, DEPTH,
                                     (long long)SS * DD, DEPTH,
                                     HH, 1.f);
    }

    // 5) Output projection: [4096,1024] @ [1024,1024] + bias -> out
    {
        dim3 grid(DD / 64, M / 64, 1), blk(256);
        gemm64<false><<<grid, blk>>>(Ctx, wo, bo, out, M, DD, DD, DD, DD, DD,
                                     0, 0, 0, 0, 0, 0, 1, 1.f);
    }
}

// round 2
// speedup vs baseline: 2.8796x; 2.8796x over previous
#include <cuda_runtime.h>
#include <cuda_bf16.h>
#include <cstdint>

// Problem constants
#define BB 2
#define SS 2048
#define DD 1024
#define HH 16
#define DEPTH 64

#define OUT_ELEMS   (BB * SS * DD)                    // 4,194,304
#define ATTN_ELEMS  ((long long)BB * HH * SS * SS)    // 134,217,728

// Scratch (device globals; no allocation in kernel_launch)
__device__ float g_Qp[BB * SS * DD];
__device__ float g_Kp[BB * SS * DD];
__device__ float g_Vp[BB * SS * DD];
__device__ float g_Ctx[BB * SS * DD];
__device__ float g_AttnScratch[BB * HH * SS * SS];    // fallback if attn not in d_out

// fp32 -> tf32 with round-to-nearest
__device__ __forceinline__ uint32_t f2tf(float x) {
    uint32_t r;
    asm("cvt.rna.tf32.f32 %0, %1;" : "=r"(r) : "f"(x));
    return r;
}

// ---------------------------------------------------------------------------
// TF32 tensor-core GEMM: C = alpha * A @ op(B) (+ bias)
//   A: [M,K] row-major lda
//   B: !TRANSB -> [K,N] ldb ; TRANSB -> [N,K] ldb (A @ B^T)
// Tiles: BM=128, BN=64, BK=16. 256 threads = 8 warps, each warp 32x32
// (2 x m16 tiles x 4 x n8 tiles of mma.sync.m16n8k8.tf32).
// Batched over blockIdx.z with per-b / per-h strides.
// Requires M%128==0, N%64==0, K%16==0 (true for all our shapes).
// ---------------------------------------------------------------------------
template <bool TRANSB>
__global__ void __launch_bounds__(256)
mma_gemm(const float* __restrict__ A, const float* __restrict__ B,
         const float* __restrict__ bias, float* __restrict__ C,
         int M, int N, int K, int lda, int ldb, int ldc,
         long long sAb, long long sAh, long long sBb, long long sBh,
         long long sCb, long long sCh, int Hn, float alpha)
{
    constexpr int BM = 128, BN = 64, BK = 16;
    __shared__ uint32_t As[BM][BK + 4];   // [m][k], row stride 20 words
    __shared__ uint32_t Bs[BK][72];       // [k][n], row stride 72 words

    const int z = blockIdx.z;
    const int b = z / Hn, h = z % Hn;
    A += (long long)b * sAb + (long long)h * sAh;
    B += (long long)b * sBb + (long long)h * sBh;
    C += (long long)b * sCb + (long long)h * sCh;

    const int m0 = blockIdx.y * BM;
    const int n0 = blockIdx.x * BN;
    const int tid  = threadIdx.x;
    const int warp = tid >> 5;
    const int lane = tid & 31;
    const int wm = (warp >> 1) * 32;      // warp m-offset within block tile
    const int wn = (warp & 1) * 32;       // warp n-offset
    const int gid  = lane >> 2;           // 0..7
    const int tid4 = lane & 3;            // 0..3

    float acc[2][4][4] = {};

    for (int k0 = 0; k0 < K; k0 += BK) {
        // --- load A tile: 128x16, 512 float4, 2 per thread ---
        #pragma unroll
        for (int i = 0; i < 2; i++) {
            int f4 = tid + i * 256;
            int m = f4 >> 2, kc = (f4 & 3) * 4;
            float4 v = *(const float4*)&A[(long long)(m0 + m) * lda + (k0 + kc)];
            As[m][kc + 0] = f2tf(v.x);
            As[m][kc + 1] = f2tf(v.y);
            As[m][kc + 2] = f2tf(v.z);
            As[m][kc + 3] = f2tf(v.w);
        }
        // --- load B tile into Bs[k][n] ---
        if (TRANSB) {
            // B is [N,K]: 64 rows x 16 k = 256 float4, 1 per thread
            int n = tid >> 2, kc = (tid & 3) * 4;
            float4 v = *(const float4*)&B[(long long)(n0 + n) * ldb + (k0 + kc)];
            Bs[kc + 0][n] = f2tf(v.x);
            Bs[kc + 1][n] = f2tf(v.y);
            Bs[kc + 2][n] = f2tf(v.z);
            Bs[kc + 3][n] = f2tf(v.w);
        } else {
            // B is [K,N]: 16 rows x 64 n = 256 float4, 1 per thread
            int kk = tid >> 4, nc = (tid & 15) * 4;
            float4 v = *(const float4*)&B[(long long)(k0 + kk) * ldb + (n0 + nc)];
            Bs[kk][nc + 0] = f2tf(v.x);
            Bs[kk][nc + 1] = f2tf(v.y);
            Bs[kk][nc + 2] = f2tf(v.z);
            Bs[kk][nc + 3] = f2tf(v.w);
        }
        __syncthreads();

        #pragma unroll
        for (int ks = 0; ks < BK; ks += 8) {
            uint32_t af[2][4], bf[4][2];
            #pragma unroll
            for (int mt = 0; mt < 2; mt++) {
                int r = wm + mt * 16 + gid;
                af[mt][0] = As[r    ][ks + tid4];
                af[mt][1] = As[r + 8][ks + tid4];
                af[mt][2] = As[r    ][ks + tid4 + 4];
                af[mt][3] = As[r + 8][ks + tid4 + 4];
            }
            #pragma unroll
            for (int nt = 0; nt < 4; nt++) {
                int c = wn + nt * 8 + gid;
                bf[nt][0] = Bs[ks + tid4    ][c];
                bf[nt][1] = Bs[ks + tid4 + 4][c];
            }
            #pragma unroll
            for (int mt = 0; mt < 2; mt++)
                #pragma unroll
                for (int nt = 0; nt < 4; nt++)
                    asm volatile(
                        "mma.sync.aligned.m16n8k8.row.col.f32.tf32.tf32.f32 "
                        "{%0,%1,%2,%3}, {%4,%5,%6,%7}, {%8,%9}, {%0,%1,%2,%3};"
                        : "+f"(acc[mt][nt][0]), "+f"(acc[mt][nt][1]),
                          "+f"(acc[mt][nt][2]), "+f"(acc[mt][nt][3])
                        : "r"(af[mt][0]), "r"(af[mt][1]), "r"(af[mt][2]), "r"(af[mt][3]),
                          "r"(bf[nt][0]), "r"(bf[nt][1]));
        }
        __syncthreads();
    }

    // --- epilogue ---
    #pragma unroll
    for (int mt = 0; mt < 2; mt++) {
        int r0 = m0 + wm + mt * 16 + gid;
        #pragma unroll
        for (int nt = 0; nt < 4; nt++) {
            int c0 = n0 + wn + nt * 8 + tid4 * 2;
            float bo0 = 0.f, bo1 = 0.f;
            if (bias) { bo0 = bias[c0]; bo1 = bias[c0 + 1]; }
            C[(long long)r0 * ldc + c0]           = alpha * acc[mt][nt][0] + bo0;
            C[(long long)r0 * ldc + c0 + 1]       = alpha * acc[mt][nt][1] + bo1;
            C[(long long)(r0 + 8) * ldc + c0]     = alpha * acc[mt][nt][2] + bo0;
            C[(long long)(r0 + 8) * ldc + c0 + 1] = alpha * acc[mt][nt][3] + bo1;
        }
    }
}

// ---------------------------------------------------------------------------
// Fused mask + softmax over one attn row (length S=2048) per block.
// ---------------------------------------------------------------------------
__global__ void __launch_bounds__(256)
softmax_mask(float* __restrict__ attn, const float* __restrict__ mask)
{
    const long long row = blockIdx.x;          // 0 .. B*H*S-1
    const int qi = (int)(row % SS);
    const int b  = (int)(row / ((long long)HH * SS));
    float* p = attn + row * SS;
    const float* mrow = mask + ((long long)b * SS + qi) * SS;

    const int tid = threadIdx.x;               // 256 threads, 8 elems each
    float v[8];
    float mx = -1e30f;
    #pragma unroll
    for (int i = 0; i < 8; i++) {
        int c = tid + i * 256;
        v[i] = p[c] + mrow[c] * (-1e9f);
        mx = fmaxf(mx, v[i]);
    }

    __shared__ float red[32];
    #pragma unroll
    for (int o = 16; o > 0; o >>= 1)
        mx = fmaxf(mx, __shfl_xor_sync(0xffffffffu, mx, o));
    if ((tid & 31) == 0) red[tid >> 5] = mx;
    __syncthreads();
    if (tid < 32) {
        float t = (tid < 8) ? red[tid] : -1e30f;
        #pragma unroll
        for (int o = 4; o > 0; o >>= 1)
            t = fmaxf(t, __shfl_xor_sync(0xffffffffu, t, o));
        if (tid == 0) red[0] = t;
    }
    __syncthreads();
    mx = red[0];
    __syncthreads();

    float sum = 0.f;
    #pragma unroll
    for (int i = 0; i < 8; i++) {
        v[i] = __expf(v[i] - mx);
        sum += v[i];
    }
    #pragma unroll
    for (int o = 16; o > 0; o >>= 1)
        sum += __shfl_xor_sync(0xffffffffu, sum, o);
    if ((tid & 31) == 0) red[tid >> 5] = sum;
    __syncthreads();
    if (tid < 32) {
        float t = (tid < 8) ? red[tid] : 0.f;
        #pragma unroll
        for (int o = 4; o > 0; o >>= 1)
            t += __shfl_xor_sync(0xffffffffu, t, o);
        if (tid == 0) red[0] = t;
    }
    __syncthreads();
    const float inv = 1.f / red[0];

    #pragma unroll
    for (int i = 0; i < 8; i++)
        p[tid + i * 256] = v[i] * inv;
}

// ---------------------------------------------------------------------------
extern "C" void kernel_launch(void* const* d_in, const int* in_sizes, int n_in,
                              void* d_out, int out_size)
{
    const float* v    = (const float*)d_in[0];
    const float* k    = (const float*)d_in[1];
    const float* q    = (const float*)d_in[2];
    const float* mask = (const float*)d_in[3];
    const float* wq   = (const float*)d_in[4];
    const float* bq   = (const float*)d_in[5];
    const float* wk   = (const float*)d_in[6];
    const float* bk   = (const float*)d_in[7];
    const float* wv   = (const float*)d_in[8];
    const float* bv   = (const float*)d_in[9];
    const float* wo   = (const float*)d_in[10];
    const float* bo   = (const float*)d_in[11];

    float *Qp, *Kp, *Vp, *Ctx, *AttnScratch;
    cudaGetSymbolAddress((void**)&Qp,  g_Qp);
    cudaGetSymbolAddress((void**)&Kp,  g_Kp);
    cudaGetSymbolAddress((void**)&Vp,  g_Vp);
    cudaGetSymbolAddress((void**)&Ctx, g_Ctx);
    cudaGetSymbolAddress((void**)&AttnScratch, g_AttnScratch);

    float* out = (float*)d_out;
    float* attn = ((long long)out_size >= (long long)OUT_ELEMS + ATTN_ELEMS)
                      ? out + OUT_ELEMS
                      : AttnScratch;

    const int M = BB * SS;              // 4096
    const float scale = 0.125f;         // 1/sqrt(64)

    // 1) Projections: [4096,1024] @ [1024,1024] + bias
    {
        dim3 grid(DD / 64, M / 128, 1), blk(256);
        mma_gemm<false><<<grid, blk>>>(q, wq, bq, Qp, M, DD, DD, DD, DD, DD,
                                       0, 0, 0, 0, 0, 0, 1, 1.f);
        mma_gemm<false><<<grid, blk>>>(k, wk, bk, Kp, M, DD, DD, DD, DD, DD,
                                       0, 0, 0, 0, 0, 0, 1, 1.f);
        mma_gemm<false><<<grid, blk>>>(v, wv, bv, Vp, M, DD, DD, DD, DD, DD,
                                       0, 0, 0, 0, 0, 0, 1, 1.f);
    }

    // 2) Logits: per (b,h): [2048,64] @ [2048,64]^T * scale -> attn
    {
        dim3 grid(SS / 64, SS / 128, BB * HH), blk(256);
        mma_gemm<true><<<grid, blk>>>(Qp, Kp, nullptr, attn,
                                      SS, SS, DEPTH, DD, DD, SS,
                                      (long long)SS * DD, DEPTH,
                                      (long long)SS * DD, DEPTH,
                                      (long long)HH * SS * SS, (long long)SS * SS,
                                      HH, scale);
    }

    // 3) Mask + softmax, in place over attn rows
    {
        dim3 grid(BB * HH * SS), blk(256);
        softmax_mask<<<grid, blk>>>(attn, mask);
    }

    // 4) Context: per (b,h): [2048,2048] @ [2048,64] -> Ctx in (b,s,h,d) layout
    {
        dim3 grid(DEPTH / 64, SS / 128, BB * HH), blk(256);
        mma_gemm<false><<<grid, blk>>>(attn, Vp, nullptr, Ctx,
                                       SS, DEPTH, SS, SS, DD, DD,
                                       (long long)HH * SS * SS, (long long)SS * SS,
                                       (long long)SS * DD, DEPTH,
                                       (long long)SS * DD, DEPTH,
                                       HH, 1.f);
    }

    // 5) Output projection: [4096,1024] @ [1024,1024] + bias -> out
    {
        dim3 grid(DD / 64, M / 128, 1), blk(256);
        mma_gemm<false><<<grid, blk>>>(Ctx, wo, bo, out, M, DD, DD, DD, DD, DD,
                                       0, 0, 0, 0, 0, 0, 1, 1.f);
    }
}